// round 15
// baseline (speedup 1.0000x reference)
#include <cuda_runtime.h>
#include <cuda_fp16.h>

// Problem shape (fixed by the reference):
//   query [4,256,256], key [4,1024,256], Wq [256,256], Wk [256,256], v [256], v_bias [1]
//   out = softmax_s( sum_h v[h]*tanh(q[bt,h]+k[bs,h]) + vb )  -> [4,256,1024] fp32
#define BSZ 4
#define TGT 256
#define SRC 1024
#define HS  256

#define Q_TILES    128      // q: (1024/64) x (256/32)
#define GEMM_TILES 640      // + k: (4096/64) x (256/32) = 512
#define GRID_X     1024     // one attn row per block

__device__ __align__(16) float  g_q[BSZ * TGT * HS];     // [1024, 256] fp32
__device__ __align__(16) __half g_kT16[BSZ * HS * SRC];  // [4, 256 h, 1024 s] fp16, TRANSPOSED

__device__ int g_gemm_done;   // arrivals from gemm tiles (reset by last block)
__device__ int g_done;        // block completions (for self-reset)

// ---------------------------------------------------------------------------
typedef unsigned long long u64t;

__device__ __forceinline__ u64t f2pack(float lo, float hi) {
    u64t r; asm("mov.b64 %0, {%1, %2};" : "=l"(r) : "f"(lo), "f"(hi)); return r;
}
__device__ __forceinline__ void f2unpack(u64t p, float& lo, float& hi) {
    asm("mov.b64 {%0, %1}, %2;" : "=f"(lo), "=f"(hi) : "l"(p));
}
__device__ __forceinline__ u64t f2fma(u64t a, u64t b, u64t c) {
    u64t r; asm("fma.rn.f32x2 %0, %1, %2, %3;" : "=l"(r) : "l"(a), "l"(b), "l"(c)); return r;
}
__device__ __forceinline__ __half2 tanh_h2(__half2 x) {
    __half2 y;
    asm("tanh.approx.f16x2 %0, %1;"
        : "=r"(*(unsigned int*)&y) : "r"(*(const unsigned int*)&x));
    return y;
}

// ---------------------------------------------------------------------------
// Fused persistent kernel. 1024 blocks x 256 threads, 6 blocks/SM guaranteed
// (wave 1 = 888 blocks >= all 640 gemm tiles -> flag barrier cannot deadlock).
// Phase 1 (bid < 640): one 64x32 GEMM tile (BK=16, double-buffered, f32x2
//   FFMA, K-sequential accumulation -> bitwise-identical to prior rounds).
//   q tiles store fp32 row-major; k tiles store transposed fp16 (smem-staged,
//   coalesced).
// Barrier: __threadfence + atomicAdd arrivals; all blocks spin on the count.
// Phase 2 (all): fused energy+softmax for row bt = bid (identical math to
//   the 73 us attn kernel).
// ---------------------------------------------------------------------------
__global__ void __launch_bounds__(256, 6)
fused_kernel(const float* __restrict__ query, const float* __restrict__ key,
             const float* __restrict__ Wq,    const float* __restrict__ Wk,
             const float* __restrict__ v,     const float* __restrict__ vbias,
             float* __restrict__ out) {
    __shared__ __align__(16) float smem_f[3072];   // 12 KB, phase-shared
#define SA(st, k, m) smem_f[(st) * 1024 + (k) * 64 + (m)]
#define SB(st, k, n) smem_f[2048 + (st) * 512 + (k) * 32 + (n)]

    const int bid = blockIdx.x;
    const int tid = threadIdx.x;

    // ---------------- Phase 1: GEMM tile ----------------
    if (bid < GEMM_TILES) {
        const bool is_q = bid < Q_TILES;
        const float* __restrict__ A;
        const float* __restrict__ B;
        int local;
        if (is_q) { A = query; B = Wq; local = bid; }
        else      { A = key;   B = Wk; local = bid - Q_TILES; }
        const int bm0 = (local >> 3) * 64;   // m (row of A / s for k)
        const int bn0 = (local & 7) * 32;    // n (output col / h for k)

        const int arow = tid >> 2, ac4 = (tid & 3) << 2;   // A: 64 rows x 4 cols
        const int brow = tid >> 3, bc2 = (tid & 7) << 1;   // B: 32 rows x 2 cols
        const int tpair = tid >> 3;          // 0..31 -> m pair
        const int tx    = tid & 7;           // 0..7  -> 4-col group

        const float* Ap = &A[(bm0 + arow) * HS + ac4];
        const float* Bp = &B[(bn0 + brow) * HS + bc2];

        u64t acc[4];
#pragma unroll
        for (int j = 0; j < 4; j++) acc[j] = f2pack(0.f, 0.f);

        float4 pa = *(const float4*)Ap;
        float2 pb = *(const float2*)Bp;
        SA(0, ac4 + 0, arow) = pa.x; SA(0, ac4 + 1, arow) = pa.y;
        SA(0, ac4 + 2, arow) = pa.z; SA(0, ac4 + 3, arow) = pa.w;
        SB(0, bc2 + 0, brow) = pb.x; SB(0, bc2 + 1, brow) = pb.y;
        __syncthreads();

#pragma unroll 4
        for (int i = 0; i < 16; i++) {
            const int st = i & 1;
            if (i < 15) {
                pa = *(const float4*)(Ap + (i + 1) * 16);
                pb = *(const float2*)(Bp + (i + 1) * 16);
            }
#pragma unroll
            for (int kk = 0; kk < 16; kk++) {
                float2 ar = ((const float2*)&SA(st, kk, 0))[tpair];
                float4 br = ((const float4*)&SB(st, kk, 0))[tx];
                u64t am = f2pack(ar.x, ar.y);
                acc[0] = f2fma(am, f2pack(br.x, br.x), acc[0]);
                acc[1] = f2fma(am, f2pack(br.y, br.y), acc[1]);
                acc[2] = f2fma(am, f2pack(br.z, br.z), acc[2]);
                acc[3] = f2fma(am, f2pack(br.w, br.w), acc[3]);
            }
            if (i < 15) {
                const int nst = st ^ 1;
                SA(nst, ac4 + 0, arow) = pa.x; SA(nst, ac4 + 1, arow) = pa.y;
                SA(nst, ac4 + 2, arow) = pa.z; SA(nst, ac4 + 3, arow) = pa.w;
                SB(nst, bc2 + 0, brow) = pb.x; SB(nst, bc2 + 1, brow) = pb.y;
                __syncthreads();
            }
        }

        float r0[4], r1[4];                  // rows m0, m0+1
#pragma unroll
        for (int j = 0; j < 4; j++) f2unpack(acc[j], r0[j], r1[j]);

        if (is_q) {
            const int m0 = bm0 + tpair * 2;
            *(float4*)&g_q[(m0 + 0) * HS + bn0 + tx * 4] = make_float4(r0[0], r0[1], r0[2], r0[3]);
            *(float4*)&g_q[(m0 + 1) * HS + bn0 + tx * 4] = make_float4(r1[0], r1[1], r1[2], r1[3]);
        } else {
            __syncthreads();                 // done with SA/SB
            __half* hst = (__half*)smem_f;   // [32 n][72] staging (144B rows)
#pragma unroll
            for (int j = 0; j < 4; j++) {
                const int h = tx * 4 + j;
                hst[h * 72 + tpair * 2 + 0] = __float2half_rn(r0[j]);
                hst[h * 72 + tpair * 2 + 1] = __float2half_rn(r1[j]);
            }
            __syncthreads();
            const int hl  = tid >> 3;        // 0..31 local h
            const int seg = tid & 7;         // 8 halves each
            const int bb  = bm0 >> 10;
            const int s0  = (bm0 & (SRC - 1)) + seg * 8;
            uint4 w = *(const uint4*)(hst + hl * 72 + seg * 8);
            *(uint4*)(g_kT16 + ((size_t)bb * HS + bn0 + hl) * SRC + s0) = w;
        }

        __threadfence();
        __syncthreads();
        if (tid == 0) atomicAdd(&g_gemm_done, 1);
    }

    // ---------------- Barrier: wait for all gemm tiles ----------------
    if (tid == 0) {
        while (*(volatile int*)&g_gemm_done < GEMM_TILES) __nanosleep(64);
    }
    __syncthreads();
    __threadfence();

    // ---------------- Phase 2: energy + softmax for row bt = bid ----------
    __half2* sq2 = (__half2*)smem_f;          // 256 pairs, 1 KB
    __half2* sv2 = (__half2*)(smem_f + 256);  // 256 pairs, 1 KB
    float*   red = smem_f + 512;              // 8 floats

    const int bt = bid;
    const int b  = bt >> 8;

    {
        const float qh = g_q[bt * HS + tid];
        const float vh = v[tid];
        sq2[tid] = __float2half2_rn(qh);
        sv2[tid] = __float2half2_rn(vh);
    }
    __syncthreads();

    const uint2* __restrict__ kp =
        ((const uint2*)(g_kT16 + (size_t)b * HS * SRC)) + tid;

    float f0 = 0.f, f1 = 0.f, f2 = 0.f, f3 = 0.f;

    for (int c = 0; c < 16; c++) {            // 16 chunks x 16 h
        uint2 kk[16];
#pragma unroll
        for (int r = 0; r < 16; r++)          // front-batched, MLP=16
            kk[r] = kp[(c * 16 + r) * (SRC / 4)];

        const __half2 z = __float2half2_rn(0.f);
        __half2 a01[2] = { z, z };
        __half2 a23[2] = { z, z };
#pragma unroll
        for (int u4 = 0; u4 < 4; u4++) {
            const int h4 = c * 4 + u4;
            uint4 qb  = ((const uint4*)sq2)[h4];
            uint4 vbq = ((const uint4*)sv2)[h4];
            const unsigned qs[4] = { qb.x, qb.y, qb.z, qb.w };
            const unsigned vs[4] = { vbq.x, vbq.y, vbq.z, vbq.w };
#pragma unroll
            for (int u = 0; u < 4; u++) {
                __half2 q2  = *(const __half2*)&qs[u];
                __half2 v2  = *(const __half2*)&vs[u];
                __half2 k01 = *(const __half2*)&kk[u4 * 4 + u].x;
                __half2 k23 = *(const __half2*)&kk[u4 * 4 + u].y;
                __half2 t01 = tanh_h2(__hadd2(q2, k01));
                __half2 t23 = tanh_h2(__hadd2(q2, k23));
                a01[u & 1] = __hfma2(v2, t01, a01[u & 1]);
                a23[u & 1] = __hfma2(v2, t23, a23[u & 1]);
            }
        }
        float2 pa = __half22float2(a01[0]);
        float2 pb = __half22float2(a01[1]);
        float2 pc = __half22float2(a23[0]);
        float2 pd = __half22float2(a23[1]);
        f0 += pa.x + pb.x; f1 += pa.y + pb.y;
        f2 += pc.x + pd.x; f3 += pc.y + pd.y;
    }

    const float vb = vbias[0];
    float sc[4] = { f0 + vb, f1 + vb, f2 + vb, f3 + vb };

    const int lane = tid & 31, wid = tid >> 5;

    float m = fmaxf(fmaxf(sc[0], sc[1]), fmaxf(sc[2], sc[3]));
#pragma unroll
    for (int o = 16; o > 0; o >>= 1) m = fmaxf(m, __shfl_xor_sync(0xffffffffu, m, o));
    if (lane == 0) red[wid] = m;
    __syncthreads();
    m = red[0];
#pragma unroll
    for (int i = 1; i < 8; i++) m = fmaxf(m, red[i]);
    __syncthreads();

    float e[4];
    float ssum = 0.f;
#pragma unroll
    for (int j = 0; j < 4; j++) { e[j] = __expf(sc[j] - m); ssum += e[j]; }
#pragma unroll
    for (int o = 16; o > 0; o >>= 1) ssum += __shfl_xor_sync(0xffffffffu, ssum, o);
    if (lane == 0) red[wid] = ssum;
    __syncthreads();
    float total = red[0];
#pragma unroll
    for (int i = 1; i < 8; i++) total += red[i];
    const float inv = __fdividef(1.0f, total);

    float4 o4 = make_float4(e[0] * inv, e[1] * inv, e[2] * inv, e[3] * inv);
    *(float4*)(out + (size_t)bt * SRC + tid * 4) = o4;

    // ---------------- Self-reset (last block out resets counters) ---------
    __syncthreads();
    if (tid == 0) {
        int d = atomicAdd(&g_done, 1);
        if (d == GRID_X - 1) { g_done = 0; g_gemm_done = 0; }
    }
#undef SA
#undef SB
}

// ---------------------------------------------------------------------------
extern "C" void kernel_launch(void* const* d_in, const int* in_sizes, int n_in,
                              void* d_out, int out_size) {
    const float* query = (const float*)d_in[0];  // [4,256,256]
    const float* key   = (const float*)d_in[1];  // [4,1024,256]
    const float* Wq    = (const float*)d_in[2];  // [256,256]
    const float* Wk    = (const float*)d_in[3];  // [256,256]
    const float* v     = (const float*)d_in[4];  // [256]
    const float* vb    = (const float*)d_in[5];  // [1]
    float* out = (float*)d_out;                  // [4,256,1024]

    fused_kernel<<<GRID_X, 256>>>(query, key, Wq, Wk, v, vb, out);
}